// round 8
// baseline (speedup 1.0000x reference)
#include <cuda_runtime.h>
#include <stdint.h>

#define BN_EPS 1e-5f

namespace {
constexpr int Nn = 64, C = 256, H = 56, W = 56;
constexpr int HP = 58, WPAD = 58;
constexpr int PIXA = HP * WPAD;              // 3364 padded pixels
constexpr int WORDS = 8;
constexpr int KW = 72;
constexpr int TH = 8;
constexpr int ROWSTR = 34;
constexpr int PLANE = 10 * ROWSTR;           // 340
constexpr int GP = 6;                        // popc groups; groups GP..7 use dp4a
constexpr long long PIXWORDS = (long long)Nn * PIXA * WORDS;
// dynamic smem layout (bytes)
constexpr int XS_OFF = 0;                    // sign bitplane tile  10,880
constexpr int AUX_OFF = 10880;               // conv2: nz tile / conv1: D0 table
constexpr int X8_OFF = 21760;                // int8 tile 10*34*256 = 87,040
constexpr int BN_OFF = X8_OFF + 10 * 34 * 256;   // 108,800: sc[256], sh[256]
constexpr int DYN = BN_OFF + 2048;           // 110,848
}

__device__ uint32_t g_s1[Nn * PIXA * WORDS];
__device__ uint32_t g_s2[Nn * PIXA * WORDS];
__device__ uint32_t g_z2[Nn * PIXA * WORDS];
__device__ uint32_t g_wb1[C * KW];
__device__ uint32_t g_wb2[C * KW];
__device__ int8_t g_a8_1[(size_t)Nn * PIXA * C];   // int8 activations, padded
__device__ int8_t g_a8_2[(size_t)Nn * PIXA * C];
__device__ int8_t g_w8_1[(size_t)C * 9 * C];       // [co][tap][ci]
__device__ int8_t g_w8_2[(size_t)C * 9 * C];
__device__ int g_D0[9 * C];
__device__ float g_sc1[C], g_sh1[C], g_sc2[C], g_sh2[C];

__device__ __forceinline__ void fa(uint32_t a, uint32_t b, uint32_t c,
                                   uint32_t& s, uint32_t& cy) {
    s = a ^ b ^ c;
    cy = (a & b) | (c & (a | b));
}
__device__ __forceinline__ void madacc2(int& a, int p) {
    asm("mad.lo.s32 %0, %1, 2, %0;" : "+r"(a) : "r"(p));
}
__device__ __forceinline__ void madacc4(int& a, int p) {
    asm("mad.lo.s32 %0, %1, 4, %0;" : "+r"(a) : "r"(p));
}
__device__ __forceinline__ int madn2(int acc, int d0) {
    int r;
    asm("mad.lo.s32 %0, %1, -2, %2;" : "=r"(r) : "r"(acc), "r"(d0));
    return r;
}

__global__ void k_zero() {
    const size_t A8Q = (size_t)Nn * PIXA * C / 16;   // uint4 per a8 buffer
    const size_t BPQ = (size_t)PIXWORDS / 4;         // uint4 per bitplane
    size_t stride = (size_t)gridDim.x * blockDim.x;
    uint4 z = {0u, 0u, 0u, 0u};
    for (size_t i = blockIdx.x * (size_t)blockDim.x + threadIdx.x; i < A8Q; i += stride) {
        ((uint4*)g_a8_1)[i] = z;
        ((uint4*)g_a8_2)[i] = z;
        if (i < BPQ) {
            ((uint4*)g_s1)[i] = z;
            ((uint4*)g_z2)[i] = z;
        }
    }
}

// grid (H, Nn), block (56, 8)
__global__ void k_pack_x(const float* __restrict__ x) {
    __shared__ __align__(16) uint8_t t8[W * C];
    const int h = blockIdx.x, n = blockIdx.y;
    const int w = threadIdx.x, wd = threadIdx.y;
    const int tid = wd * W + w;
    const float* xp = x + (((size_t)n * C + wd * 32) * H + h) * W + w;
    uint8_t* tp = t8 + w * C + wd * 32;
    uint32_t s = 0;
#pragma unroll
    for (int ci = 0; ci < 32; ci++) {
        float v = xp[(size_t)ci * (H * W)];
        s |= (v > 0.f ? 1u : 0u) << ci;
        tp[ci] = (uint8_t)(int8_t)((v > 0.f) - (v < 0.f));
    }
    g_s1[(((size_t)n * PIXA) + (h + 1) * WPAD + (w + 1)) * WORDS + wd] = s;
    __syncthreads();
    for (int i = tid; i < W * 16; i += W * 8) {
        int pw = i >> 4, q = i & 15;
        uint4 v = ((const uint4*)t8)[i];
        *(uint4*)(g_a8_1 + ((((size_t)n * PIXA) + (h + 1) * WPAD + pw + 1) << 8) + (q << 4)) = v;
    }
}

// grid C, block (8, 9)
__global__ void k_pack_w(const float* __restrict__ w, int which) {
    uint32_t* __restrict__ outw = which ? g_wb2 : g_wb1;
    int8_t* __restrict__ out8 = which ? g_w8_2 : g_w8_1;
    const int co = blockIdx.x, wd = threadIdx.x, tap = threadIdx.y;
    uint32_t s = 0;
#pragma unroll
    for (int ci = 0; ci < 32; ci++) {
        float v = w[(((size_t)co * C) + wd * 32 + ci) * 9 + tap];
        s |= (v > 0.f ? 1u : 0u) << ci;
        out8[((size_t)co * 9 + tap) * C + wd * 32 + ci] = (int8_t)((v > 0.f) - (v < 0.f));
    }
    outw[co * KW + tap * WORDS + wd] = s;
}

__global__ void k_prep_d0() {
    const int co = threadIdx.x;
    int pc[9];
#pragma unroll
    for (int t = 0; t < 9; t++) {
        int s = 0;
#pragma unroll
        for (int wd = 0; wd < WORDS; wd++) s += __popc(g_wb1[co * KW + t * WORDS + wd]);
        pc[t] = s;
    }
#pragma unroll
    for (int cs = 0; cs < 9; cs++) {
        int hc = cs / 3, wc = cs % 3, V = 0, P = 0;
#pragma unroll
        for (int t = 0; t < 9; t++) {
            int dh = t / 3, dw = t % 3;
            bool inval = (dh == 0 && hc == 0) || (dh == 2 && hc == 2) ||
                         (dw == 0 && wc == 0) || (dw == 2 && wc == 2);
            if (inval) P += pc[t]; else V++;
        }
        g_D0[cs * C + co] = 256 * V + 2 * P;
    }
}

__global__ void k_prep_bn(const float* __restrict__ g, const float* __restrict__ b,
                          const float* __restrict__ m, const float* __restrict__ v,
                          int which) {
    int c = threadIdx.x;
    float sc = g[c] * rsqrtf(v[c] + BN_EPS);
    float sh = b[c] - m[c] * sc;
    if (which) { g_sc2[c] = sc; g_sh2[c] = sh; }
    else       { g_sc1[c] = sc; g_sh1[c] = sh; }
}

// ---------------- conv1: popc (groups 0..GP-1, D0 borders) + dp4a (rest) ----------------
__global__ __launch_bounds__(256, 2) void k_bconv1() {
    extern __shared__ char sm[];
    uint32_t* xs = (uint32_t*)(sm + XS_OFF);
    int* d0s = (int*)(sm + AUX_OFF);
    float* scs = (float*)(sm + BN_OFF);
    float* shs = scs + C;

    const int chunkb = blockIdx.x, h0 = blockIdx.y * TH, n = blockIdx.z;
    const int tid = threadIdx.x, w0 = chunkb * 32;

    for (int i = tid; i < WORDS * PLANE; i += 256) {
        int wd = i & 7, c = (i >> 3) % ROWSTR, r = (i >> 3) / ROWSTR;
        int col = w0 + c;
        uint32_t s = 0;
        if (col < WPAD)
            s = g_s1[(((size_t)n * PIXA) + (h0 + r) * WPAD + col) * WORDS + wd];
        xs[wd * PLANE + r * ROWSTR + c] = s;
    }
    for (int g = tid; g < 10 * 34 * 16; g += 256) {
        int pix = g >> 4, ck = g & 15;
        int row = pix / 34, col = pix % 34;
        uint4 v = {0u, 0u, 0u, 0u};
        int gcol = w0 + col;
        if (gcol < WPAD)
            v = *(const uint4*)(g_a8_1 + ((((size_t)n * PIXA) + (h0 + row) * WPAD + gcol) << 8) + (ck << 4));
        *(uint4*)(sm + X8_OFF + pix * 256 + ((ck ^ (col & 7)) << 4)) = v;
    }
    for (int i = tid; i < 9 * C; i += 256) d0s[i] = g_D0[i];
    if (tid < C) { scs[tid] = g_sc1[tid]; shs[tid] = g_sh1[tid]; }
    __syncthreads();

    const int lane = tid & 31, wid = tid >> 5;
    const int ow = w0 + lane;
    const bool act = (ow < W);
    const int wc = (ow == 0) ? 0 : (ow == W - 1) ? 2 : 1;

    uint32_t osig[TH], onz[TH];
#pragma unroll
    for (int r = 0; r < TH; r++) { osig[r] = 0u; onz[r] = 0u; }

    // ---- popc groups ----
    for (int grp = 0; grp < GP; grp++) {
        const int j0 = grp * 4;
        int acc[4][TH];
#pragma unroll
        for (int jj = 0; jj < 4; jj++)
#pragma unroll
            for (int r = 0; r < TH; r++) acc[jj][r] = 0;

        const uint32_t* wp = g_wb1 + (wid * 32 + j0) * KW;
        for (int g = 0; g < 8; g++) {
            uint32_t wk[4][9];
#pragma unroll
            for (int c4 = 0; c4 < 4; c4++)
#pragma unroll
                for (int t = 0; t < 9; t++) wk[c4][t] = __ldg(wp + c4 * KW + g * 9 + t);
            int off[9];
#pragma unroll
            for (int q = 0; q < 9; q++) {
                int k = g * 9 + q;
                int wd = k & 7, tap = k >> 3;
                off[q] = wd * PLANE + (tap / 3) * ROWSTR + (tap % 3) + lane;
            }
#pragma unroll
            for (int r = 0; r < TH; r++) {
                uint32_t sA[4][3], cA[4][3];
#pragma unroll
                for (int t3 = 0; t3 < 3; t3++) {
                    uint32_t x0 = xs[off[t3 * 3 + 0] + r * ROWSTR];
                    uint32_t x1 = xs[off[t3 * 3 + 1] + r * ROWSTR];
                    uint32_t x2 = xs[off[t3 * 3 + 2] + r * ROWSTR];
#pragma unroll
                    for (int c4 = 0; c4 < 4; c4++)
                        fa(x0 ^ wk[c4][t3 * 3 + 0], x1 ^ wk[c4][t3 * 3 + 1],
                           x2 ^ wk[c4][t3 * 3 + 2], sA[c4][t3], cA[c4][t3]);
                }
#pragma unroll
                for (int c4 = 0; c4 < 4; c4++) {
                    uint32_t S, C2, S2, C4w;
                    fa(sA[c4][0], sA[c4][1], sA[c4][2], S, C2);
                    fa(cA[c4][0], cA[c4][1], cA[c4][2], S2, C4w);
                    int a = acc[c4][r];
                    a += __popc(S);
                    madacc2(a, __popc(C2) + __popc(S2));
                    madacc4(a, __popc(C4w));
                    acc[c4][r] = a;
                }
            }
        }
#pragma unroll
        for (int r = 0; r < TH; r++) {
            const int h = h0 + r;
            const int hc = (h == 0) ? 0 : (h == H - 1) ? 2 : 1;
            uint32_t b4 = 0;
#pragma unroll
            for (int jj = 0; jj < 4; jj++) {
                const int co = wid * 32 + j0 + jj;
                const int dot = madn2(acc[jj][r], d0s[(hc * 3 + wc) * C + co]);
                const float t = fmaf((float)dot, scs[co], shs[co]);
                osig[r] |= (t > 0.f ? 1u : 0u) << (j0 + jj);
                onz[r] |= (t != 0.f ? 1u : 0u) << (j0 + jj);
                uint32_t byte = (t > 0.f) ? 1u : ((t < 0.f) ? 0xFFu : 0u);
                b4 |= byte << (8 * jj);
            }
            if (act)
                *(uint32_t*)(g_a8_2 + ((((size_t)n * PIXA) + (h + 1) * WPAD + ow + 1) << 8) +
                             wid * 32 + j0) = b4;
        }
    }

    // ---- dp4a groups (fma pipe) ----
    for (int grp = GP; grp < 8; grp++) {
        const int j0 = grp * 4;
        int acc[4][TH];
#pragma unroll
        for (int jj = 0; jj < 4; jj++)
#pragma unroll
            for (int r = 0; r < TH; r++) acc[jj][r] = 0;

        const int8_t* wb8 = g_w8_1 + (size_t)(wid * 32 + j0) * 9 * 256;
#pragma unroll 1
        for (int tap = 0; tap < 9; tap++) {
            const int dh = tap / 3, dw = tap % 3;
            const int colx = lane + dw;
            const char* xrow = sm + X8_OFF + (dh * 34 + colx) * 256;
            const uint32_t swz = (uint32_t)(colx & 7) << 4;
#pragma unroll 1
            for (int ck = 0; ck < 16; ck++) {
                uint4 wv[4];
#pragma unroll
                for (int c4 = 0; c4 < 4; c4++)
                    wv[c4] = __ldg((const uint4*)(wb8 + c4 * 2304 + tap * 256 + ck * 16));
                const uint32_t xoff = ((uint32_t)ck << 4) ^ swz;
#pragma unroll
                for (int r = 0; r < TH; r++) {
                    uint4 xv = *(const uint4*)(xrow + r * (34 * 256) + xoff);
#pragma unroll
                    for (int c4 = 0; c4 < 4; c4++) {
                        int a = acc[c4][r];
                        a = __dp4a((int)xv.x, (int)wv[c4].x, a);
                        a = __dp4a((int)xv.y, (int)wv[c4].y, a);
                        a = __dp4a((int)xv.z, (int)wv[c4].z, a);
                        a = __dp4a((int)xv.w, (int)wv[c4].w, a);
                        acc[c4][r] = a;
                    }
                }
            }
        }
#pragma unroll
        for (int r = 0; r < TH; r++) {
            uint32_t b4 = 0;
#pragma unroll
            for (int jj = 0; jj < 4; jj++) {
                const int co = wid * 32 + j0 + jj;
                const float t = fmaf((float)acc[jj][r], scs[co], shs[co]);
                osig[r] |= (t > 0.f ? 1u : 0u) << (j0 + jj);
                onz[r] |= (t != 0.f ? 1u : 0u) << (j0 + jj);
                uint32_t byte = (t > 0.f) ? 1u : ((t < 0.f) ? 0xFFu : 0u);
                b4 |= byte << (8 * jj);
            }
            if (act)
                *(uint32_t*)(g_a8_2 + ((((size_t)n * PIXA) + (h0 + r + 1) * WPAD + ow + 1) << 8) +
                             wid * 32 + j0) = b4;
        }
    }

    if (act) {
#pragma unroll
        for (int r = 0; r < TH; r++) {
            size_t gi = (((size_t)n * PIXA) + (h0 + r + 1) * WPAD + (ow + 1)) * WORDS + wid;
            g_s2[gi] = osig[r];
            g_z2[gi] = onz[r];
        }
    }
}

// ---------------- conv2: popc (nz plane) + dp4a; residual + clamp ----------------
__global__ __launch_bounds__(256, 2) void k_bconv2(const float* __restrict__ xres,
                                                   float* __restrict__ out) {
    extern __shared__ char sm[];
    uint32_t* xs = (uint32_t*)(sm + XS_OFF);
    uint32_t* xz = (uint32_t*)(sm + AUX_OFF);
    float* scs = (float*)(sm + BN_OFF);
    float* shs = scs + C;

    const int chunkb = blockIdx.x, h0 = blockIdx.y * TH, n = blockIdx.z;
    const int tid = threadIdx.x, w0 = chunkb * 32;

    for (int i = tid; i < WORDS * PLANE; i += 256) {
        int wd = i & 7, c = (i >> 3) % ROWSTR, r = (i >> 3) / ROWSTR;
        int col = w0 + c;
        uint32_t s = 0, z = 0;
        if (col < WPAD) {
            size_t gi = (((size_t)n * PIXA) + (h0 + r) * WPAD + col) * WORDS + wd;
            s = g_s2[gi];
            z = g_z2[gi];
        }
        xs[wd * PLANE + r * ROWSTR + c] = s;
        xz[wd * PLANE + r * ROWSTR + c] = z;
    }
    for (int g = tid; g < 10 * 34 * 16; g += 256) {
        int pix = g >> 4, ck = g & 15;
        int row = pix / 34, col = pix % 34;
        uint4 v = {0u, 0u, 0u, 0u};
        int gcol = w0 + col;
        if (gcol < WPAD)
            v = *(const uint4*)(g_a8_2 + ((((size_t)n * PIXA) + (h0 + row) * WPAD + gcol) << 8) + (ck << 4));
        *(uint4*)(sm + X8_OFF + pix * 256 + ((ck ^ (col & 7)) << 4)) = v;
    }
    if (tid < C) { scs[tid] = g_sc2[tid]; shs[tid] = g_sh2[tid]; }
    __syncthreads();

    const int lane = tid & 31, wid = tid >> 5;
    const int ow = w0 + lane;
    const bool act = (ow < W);

    int base[TH];
#pragma unroll
    for (int r = 0; r < TH; r++) base[r] = 0;
    for (int g = 0; g < 8; g++) {
        int off[9];
#pragma unroll
        for (int q = 0; q < 9; q++) {
            int k = g * 9 + q;
            int wd = k & 7, tap = k >> 3;
            off[q] = wd * PLANE + (tap / 3) * ROWSTR + (tap % 3) + lane;
        }
#pragma unroll
        for (int r = 0; r < TH; r++) {
            uint32_t s0, c0, s1, c1, s2, c2, S, C2, S2, C4;
            fa(xz[off[0] + r * ROWSTR], xz[off[1] + r * ROWSTR], xz[off[2] + r * ROWSTR], s0, c0);
            fa(xz[off[3] + r * ROWSTR], xz[off[4] + r * ROWSTR], xz[off[5] + r * ROWSTR], s1, c1);
            fa(xz[off[6] + r * ROWSTR], xz[off[7] + r * ROWSTR], xz[off[8] + r * ROWSTR], s2, c2);
            fa(s0, s1, s2, S, C2);
            fa(c0, c1, c2, S2, C4);
            int a = base[r];
            a += __popc(S);
            madacc2(a, __popc(C2) + __popc(S2));
            madacc4(a, __popc(C4));
            base[r] = a;
        }
    }

    for (int grp = 0; grp < GP; grp++) {
        const int j0 = grp * 4;
        int acc[4][TH];
#pragma unroll
        for (int jj = 0; jj < 4; jj++)
#pragma unroll
            for (int r = 0; r < TH; r++) acc[jj][r] = 0;

        const uint32_t* wp = g_wb2 + (wid * 32 + j0) * KW;
        for (int g = 0; g < 8; g++) {
            uint32_t wk[4][9];
#pragma unroll
            for (int c4 = 0; c4 < 4; c4++)
#pragma unroll
                for (int t = 0; t < 9; t++) wk[c4][t] = __ldg(wp + c4 * KW + g * 9 + t);
            int off[9];
#pragma unroll
            for (int q = 0; q < 9; q++) {
                int k = g * 9 + q;
                int wd = k & 7, tap = k >> 3;
                off[q] = wd * PLANE + (tap / 3) * ROWSTR + (tap % 3) + lane;
            }
#pragma unroll
            for (int r = 0; r < TH; r++) {
                uint32_t sA[4][3], cA[4][3];
#pragma unroll
                for (int t3 = 0; t3 < 3; t3++) {
                    uint32_t sx0 = xs[off[t3 * 3 + 0] + r * ROWSTR];
                    uint32_t zx0 = xz[off[t3 * 3 + 0] + r * ROWSTR];
                    uint32_t sx1 = xs[off[t3 * 3 + 1] + r * ROWSTR];
                    uint32_t zx1 = xz[off[t3 * 3 + 1] + r * ROWSTR];
                    uint32_t sx2 = xs[off[t3 * 3 + 2] + r * ROWSTR];
                    uint32_t zx2 = xz[off[t3 * 3 + 2] + r * ROWSTR];
#pragma unroll
                    for (int c4 = 0; c4 < 4; c4++)
                        fa(zx0 & (sx0 ^ wk[c4][t3 * 3 + 0]),
                           zx1 & (sx1 ^ wk[c4][t3 * 3 + 1]),
                           zx2 & (sx2 ^ wk[c4][t3 * 3 + 2]),
                           sA[c4][t3], cA[c4][t3]);
                }
#pragma unroll
                for (int c4 = 0; c4 < 4; c4++) {
                    uint32_t S, C2, S2, C4w;
                    fa(sA[c4][0], sA[c4][1], sA[c4][2], S, C2);
                    fa(cA[c4][0], cA[c4][1], cA[c4][2], S2, C4w);
                    int a = acc[c4][r];
                    a += __popc(S);
                    madacc2(a, __popc(C2) + __popc(S2));
                    madacc4(a, __popc(C4w));
                    acc[c4][r] = a;
                }
            }
        }
        if (act) {
#pragma unroll
            for (int jj = 0; jj < 4; jj++) {
                const int co = wid * 32 + j0 + jj;
                const float sc = scs[co], sh = shs[co];
#pragma unroll
                for (int r = 0; r < TH; r++) {
                    const int dot = madn2(acc[jj][r], base[r]);
                    const float t = fmaf((float)dot, sc, sh);
                    size_t oi = (((size_t)n * C + co) * H + (h0 + r)) * W + ow;
                    float v = t + xres[oi];
                    out[oi] = fminf(1.f, fmaxf(-1.f, v));
                }
            }
        }
    }

    for (int grp = GP; grp < 8; grp++) {
        const int j0 = grp * 4;
        int acc[4][TH];
#pragma unroll
        for (int jj = 0; jj < 4; jj++)
#pragma unroll
            for (int r = 0; r < TH; r++) acc[jj][r] = 0;

        const int8_t* wb8 = g_w8_2 + (size_t)(wid * 32 + j0) * 9 * 256;
#pragma unroll 1
        for (int tap = 0; tap < 9; tap++) {
            const int dh = tap / 3, dw = tap % 3;
            const int colx = lane + dw;
            const char* xrow = sm + X8_OFF + (dh * 34 + colx) * 256;
            const uint32_t swz = (uint32_t)(colx & 7) << 4;
#pragma unroll 1
            for (int ck = 0; ck < 16; ck++) {
                uint4 wv[4];
#pragma unroll
                for (int c4 = 0; c4 < 4; c4++)
                    wv[c4] = __ldg((const uint4*)(wb8 + c4 * 2304 + tap * 256 + ck * 16));
                const uint32_t xoff = ((uint32_t)ck << 4) ^ swz;
#pragma unroll
                for (int r = 0; r < TH; r++) {
                    uint4 xv = *(const uint4*)(xrow + r * (34 * 256) + xoff);
#pragma unroll
                    for (int c4 = 0; c4 < 4; c4++) {
                        int a = acc[c4][r];
                        a = __dp4a((int)xv.x, (int)wv[c4].x, a);
                        a = __dp4a((int)xv.y, (int)wv[c4].y, a);
                        a = __dp4a((int)xv.z, (int)wv[c4].z, a);
                        a = __dp4a((int)xv.w, (int)wv[c4].w, a);
                        acc[c4][r] = a;
                    }
                }
            }
        }
        if (act) {
#pragma unroll
            for (int jj = 0; jj < 4; jj++) {
                const int co = wid * 32 + j0 + jj;
                const float sc = scs[co], sh = shs[co];
#pragma unroll
                for (int r = 0; r < TH; r++) {
                    const float t = fmaf((float)acc[jj][r], sc, sh);
                    size_t oi = (((size_t)n * C + co) * H + (h0 + r)) * W + ow;
                    float v = t + xres[oi];
                    out[oi] = fminf(1.f, fmaxf(-1.f, v));
                }
            }
        }
    }
}

extern "C" void kernel_launch(void* const* d_in, const int* in_sizes, int n_in,
                              void* d_out, int out_size) {
    (void)in_sizes; (void)n_in; (void)out_size;
    const float* x = (const float*)d_in[0];
    const float* w1 = (const float*)d_in[1];
    const float* g1 = (const float*)d_in[2];
    const float* b1 = (const float*)d_in[3];
    const float* m1 = (const float*)d_in[4];
    const float* v1 = (const float*)d_in[5];
    const float* w2 = (const float*)d_in[6];
    const float* g2 = (const float*)d_in[7];
    const float* b2 = (const float*)d_in[8];
    const float* m2 = (const float*)d_in[9];
    const float* v2 = (const float*)d_in[10];
    float* out = (float*)d_out;

    cudaFuncSetAttribute(k_bconv1, cudaFuncAttributeMaxDynamicSharedMemorySize, DYN);
    cudaFuncSetAttribute(k_bconv2, cudaFuncAttributeMaxDynamicSharedMemorySize, DYN);

    k_zero<<<2048, 256>>>();
    k_pack_x<<<dim3(H, Nn), dim3(W, WORDS)>>>(x);
    k_pack_w<<<C, dim3(WORDS, 9)>>>(w1, 0);
    k_pack_w<<<C, dim3(WORDS, 9)>>>(w2, 1);
    k_prep_d0<<<1, C>>>();
    k_prep_bn<<<1, C>>>(g1, b1, m1, v1, 0);
    k_prep_bn<<<1, C>>>(g2, b2, m2, v2, 1);

    dim3 grid(2, H / TH, Nn);
    k_bconv1<<<grid, 256, DYN>>>();
    k_bconv2<<<grid, 256, DYN>>>(x, out);
}

// round 9
// speedup vs baseline: 1.4168x; 1.4168x over previous
#include <cuda_runtime.h>
#include <stdint.h>

#define BN_EPS 1e-5f

namespace {
constexpr int Nn = 64, C = 256, H = 56, W = 56;
constexpr int HP = H + 2, WPAD = W + 2;          // zero-padded bitplane dims
constexpr int WORDS = C / 32;                     // 8 words of channel bits
constexpr int KW = 9 * WORDS;                     // 72 (tap, word) pairs
constexpr int TH = 8;                             // output rows per block
constexpr int ROWSTR = 34;                        // smem row stride (words)
constexpr int PLANE = (TH + 2) * ROWSTR;          // 340 per channel-word plane
constexpr long long PIXWORDS = (long long)Nn * HP * WPAD * WORDS;
}

__device__ uint32_t g_s1[Nn * HP * WPAD * WORDS];
__device__ uint32_t g_z1[Nn * HP * WPAD * WORDS];
__device__ uint32_t g_s2[Nn * HP * WPAD * WORDS];
__device__ uint32_t g_z2[Nn * HP * WPAD * WORDS];
__device__ uint32_t g_wb1[C * KW];
__device__ uint32_t g_wb2[C * KW];
__device__ float g_sc1[C], g_sh1[C], g_sc2[C], g_sh2[C];

// Full adder: 3 words -> sum (weight w) + carry (weight 2w). One LOP3 each.
__device__ __forceinline__ void fa(uint32_t a, uint32_t b, uint32_t c,
                                   uint32_t& s, uint32_t& cy) {
    s = a ^ b ^ c;
    cy = (a & b) | (c & (a | b));
}

__global__ void k_zero_nz() {
    long long stride = (long long)gridDim.x * blockDim.x;
    for (long long i = blockIdx.x * (long long)blockDim.x + threadIdx.x;
         i < PIXWORDS; i += stride) {
        g_z1[i] = 0u;
        g_z2[i] = 0u;
    }
}

// Pack input activations: grid (H, N), block (W=56, WORDS=8).
__global__ void k_pack_x(const float* __restrict__ x) {
    const int h = blockIdx.x, n = blockIdx.y;
    const int w = threadIdx.x, wd = threadIdx.y;
    const float* xp = x + (((long long)n * C + wd * 32) * H + h) * W + w;
    uint32_t s = 0, z = 0;
#pragma unroll
    for (int ci = 0; ci < 32; ci++) {
        float v = xp[(long long)ci * (H * W)];
        s |= (v > 0.f ? 1u : 0u) << ci;
        z |= (v != 0.f ? 1u : 0u) << ci;
    }
    long long idx = (((long long)n * HP + (h + 1)) * WPAD + (w + 1)) * WORDS + wd;
    g_s1[idx] = s;
    g_z1[idx] = z;
}

// Pack weights: grid (C), block (WORDS=8, 9 taps).
__global__ void k_pack_w(const float* __restrict__ w, int which) {
    uint32_t* __restrict__ outw = which ? g_wb2 : g_wb1;
    const int co = blockIdx.x, wd = threadIdx.x, tap = threadIdx.y;
    uint32_t s = 0;
#pragma unroll
    for (int ci = 0; ci < 32; ci++)
        s |= (w[(((long long)co * C) + wd * 32 + ci) * 9 + tap] > 0.f ? 1u : 0u) << ci;
    outw[co * KW + tap * WORDS + wd] = s;
}

__global__ void k_prep_bn(const float* __restrict__ g, const float* __restrict__ b,
                          const float* __restrict__ m, const float* __restrict__ v,
                          int which) {
    int c = threadIdx.x;
    float sc = g[c] * rsqrtf(v[c] + BN_EPS);
    float sh = b[c] - m[c] * sc;
    if (which) { g_sc2[c] = sc; g_sh2[c] = sh; }
    else       { g_sc1[c] = sc; g_sh1[c] = sh; }
}

// Compress one 24-word unit (3 taps x 8 channel-words, input row u+r) for
// 2 output channels sharing the x loads. 18 FAs -> 6 finals {1,1,2,4,8,8}.
// Binary conv + BN (+ re-binarize or residual/clip).
// Grid: (2 w-chunks, H/TH, N). Block: 256 threads = 8 warps.
// Warp lanes = output w; warp id = output channel word (32 co per warp).
template <int STAGE>
__global__ __launch_bounds__(256, 2) void k_bconv(
    const float* __restrict__ xres, float* __restrict__ out) {
    const uint32_t* __restrict__ sIn = (STAGE == 1) ? g_s1 : g_s2;
    const uint32_t* __restrict__ zIn = (STAGE == 1) ? g_z1 : g_z2;
    const uint32_t* __restrict__ wb = (STAGE == 1) ? g_wb1 : g_wb2;
    const float* __restrict__ gsc = (STAGE == 1) ? g_sc1 : g_sc2;
    const float* __restrict__ gsh = (STAGE == 1) ? g_sh1 : g_sh2;

    __shared__ uint32_t xs[WORDS * PLANE];
    __shared__ uint32_t xz[WORDS * PLANE];
    __shared__ float scs[C], shs[C];

    const int chunk = blockIdx.x, h0 = blockIdx.y * TH, n = blockIdx.z;
    const int tid = threadIdx.x, w0 = chunk * 32;

    for (int i = tid; i < WORDS * PLANE; i += 256) {
        int wd = i & 7, c = (i >> 3) % ROWSTR, r = (i >> 3) / ROWSTR;
        int col = w0 + c;
        uint32_t s = 0, z = 0;
        if (col < WPAD) {
            long long gi = (((long long)n * HP + (h0 + r)) * WPAD + col) * WORDS + wd;
            s = sIn[gi];
            z = zIn[gi];
        }
        xs[wd * PLANE + r * ROWSTR + c] = s;
        xz[wd * PLANE + r * ROWSTR + c] = z;
    }
    if (tid < C) { scs[tid] = gsc[tid]; shs[tid] = gsh[tid]; }
    __syncthreads();

    const int lane = tid & 31, wid = tid >> 5;
    const int ow = w0 + lane;
    const bool act = (ow < W);

    // base[r] = sum popc(nz) over the 72-word window (shared by all co).
    int base[TH];
#pragma unroll
    for (int r = 0; r < TH; r++) base[r] = 0;
    for (int g = 0; g < 8; g++) {
        int off[9];
#pragma unroll
        for (int q = 0; q < 9; q++) {
            int k = g * 9 + q;
            int wd = k & 7, tap = k >> 3;
            off[q] = wd * PLANE + (tap / 3) * ROWSTR + (tap % 3) + lane;
        }
#pragma unroll
        for (int r = 0; r < TH; r++) {
            uint32_t s0, c0, s1, c1, s2, c2, S, C2, S2, C4;
            fa(xz[off[0] + r * ROWSTR], xz[off[1] + r * ROWSTR], xz[off[2] + r * ROWSTR], s0, c0);
            fa(xz[off[3] + r * ROWSTR], xz[off[4] + r * ROWSTR], xz[off[5] + r * ROWSTR], s1, c1);
            fa(xz[off[6] + r * ROWSTR], xz[off[7] + r * ROWSTR], xz[off[8] + r * ROWSTR], s2, c2);
            fa(s0, s1, s2, S, C2);
            fa(c0, c1, c2, S2, C4);
            base[r] += __popc(S) + 2 * (__popc(C2) + __popc(S2)) + 4 * __popc(C4);
        }
    }

    uint32_t osig[TH], onz[TH];
    if (STAGE == 1) {
#pragma unroll
        for (int r = 0; r < TH; r++) { osig[r] = 0u; onz[r] = 0u; }
    }

    for (int j0 = 0; j0 < 32; j0 += 2) {
        int acc[2][TH];
#pragma unroll
        for (int c = 0; c < 2; c++)
#pragma unroll
            for (int r = 0; r < TH; r++) acc[c][r] = 0;

        const uint32_t* wp = wb + (wid * 32 + j0) * KW;
        for (int u = 0; u < 3; u++) {
            // weight words for unit u: q = 0..23 maps to (wd=q&7, dw=q>>3), dh=u
            uint32_t wk0[24], wk1[24];
#pragma unroll
            for (int q = 0; q < 24; q++) {
                wk0[q] = __ldg(wp + u * 24 + q);
                wk1[q] = __ldg(wp + KW + u * 24 + q);
            }
#pragma unroll
            for (int r = 0; r < TH; r++) {
                const int rowoff = (u + r) * ROWSTR + lane;
                uint32_t A0[8], B0[8], A1[8], B1[8];
#pragma unroll
                for (int t = 0; t < 8; t++) {
                    const int q0 = 3 * t, q1 = 3 * t + 1, q2 = 3 * t + 2;
                    const int o0 = (q0 & 7) * PLANE + (q0 >> 3) + rowoff;
                    const int o1 = (q1 & 7) * PLANE + (q1 >> 3) + rowoff;
                    const int o2 = (q2 & 7) * PLANE + (q2 >> 3) + rowoff;
                    uint32_t sx0 = xs[o0], zx0 = xz[o0];
                    uint32_t sx1 = xs[o1], zx1 = xz[o1];
                    uint32_t sx2 = xs[o2], zx2 = xz[o2];
                    fa(zx0 & (sx0 ^ wk0[q0]), zx1 & (sx1 ^ wk0[q1]),
                       zx2 & (sx2 ^ wk0[q2]), A0[t], B0[t]);
                    fa(zx0 & (sx0 ^ wk1[q0]), zx1 & (sx1 ^ wk1[q1]),
                       zx2 & (sx2 ^ wk1[q2]), A1[t], B1[t]);
                }
#pragma unroll
                for (int c = 0; c < 2; c++) {
                    uint32_t* A = c ? A1 : A0;
                    uint32_t* B = c ? B1 : B0;
                    uint32_t p0, q0, p1, q1, p2, q2;
                    fa(A[0], A[1], A[2], p0, q0);
                    fa(A[3], A[4], A[5], p1, q1);
                    fa(A[6], A[7], p0, p2, q2);
                    uint32_t r0, s0, r1, s1, r2, s2, r3, s3, F2, s4, t0, u0, F4, u1;
                    fa(B[0], B[1], B[2], r0, s0);
                    fa(B[3], B[4], B[5], r1, s1);
                    fa(B[6], B[7], q0, r2, s2);
                    fa(q1, q2, r0, r3, s3);
                    fa(r1, r2, r3, F2, s4);
                    fa(s0, s1, s2, t0, u0);
                    fa(s3, s4, t0, F4, u1);
                    acc[c][r] += __popc(p1) + __popc(p2) + 2 * __popc(F2) +
                                 4 * __popc(F4) + 8 * (__popc(u0) + __popc(u1));
                }
            }
        }

#pragma unroll
        for (int jj = 0; jj < 2; jj++) {
            const int co = wid * 32 + j0 + jj;
            const float sc = scs[co], sh = shs[co];
            if (STAGE == 1) {
#pragma unroll
                for (int r = 0; r < TH; r++) {
                    float t = fmaf((float)(base[r] - 2 * acc[jj][r]), sc, sh);
                    osig[r] |= (t > 0.f ? 1u : 0u) << (j0 + jj);
                    onz[r] |= (t != 0.f ? 1u : 0u) << (j0 + jj);
                }
            } else if (act) {
#pragma unroll
                for (int r = 0; r < TH; r++) {
                    float t = fmaf((float)(base[r] - 2 * acc[jj][r]), sc, sh);
                    long long oi = (((long long)n * C + co) * H + (h0 + r)) * W + ow;
                    float v = t + xres[oi];
                    out[oi] = fminf(1.f, fmaxf(-1.f, v));
                }
            }
        }
    }

    if (STAGE == 1 && act) {
#pragma unroll
        for (int r = 0; r < TH; r++) {
            long long gi =
                (((long long)n * HP + (h0 + r + 1)) * WPAD + (ow + 1)) * WORDS + wid;
            g_s2[gi] = osig[r];
            g_z2[gi] = onz[r];
        }
    }
}

extern "C" void kernel_launch(void* const* d_in, const int* in_sizes, int n_in,
                              void* d_out, int out_size) {
    (void)in_sizes; (void)n_in; (void)out_size;
    const float* x = (const float*)d_in[0];
    const float* w1 = (const float*)d_in[1];
    const float* g1 = (const float*)d_in[2];
    const float* b1 = (const float*)d_in[3];
    const float* m1 = (const float*)d_in[4];
    const float* v1 = (const float*)d_in[5];
    const float* w2 = (const float*)d_in[6];
    const float* g2 = (const float*)d_in[7];
    const float* b2 = (const float*)d_in[8];
    const float* m2 = (const float*)d_in[9];
    const float* v2 = (const float*)d_in[10];
    float* out = (float*)d_out;

    k_zero_nz<<<1024, 256>>>();
    k_pack_x<<<dim3(H, Nn), dim3(W, WORDS)>>>(x);
    k_pack_w<<<C, dim3(WORDS, 9)>>>(w1, 0);
    k_pack_w<<<C, dim3(WORDS, 9)>>>(w2, 1);
    k_prep_bn<<<1, C>>>(g1, b1, m1, v1, 0);
    k_prep_bn<<<1, C>>>(g2, b2, m2, v2, 1);

    dim3 grid(2, H / TH, Nn);
    k_bconv<1><<<grid, 256>>>(x, out);
    k_bconv<2><<<grid, 256>>>(x, out);
}

// round 10
// speedup vs baseline: 1.4343x; 1.0123x over previous
#include <cuda_runtime.h>
#include <stdint.h>

#define BN_EPS 1e-5f

namespace {
constexpr int Nn = 64, C = 256, H = 56, W = 56;
constexpr int HP = H + 2, WPAD = W + 2;          // zero-padded bitplane dims
constexpr int WORDS = C / 32;                     // 8 words of channel bits
constexpr int KW = 9 * WORDS;                     // 72 (tap, word) pairs
constexpr int TH = 8;                             // output rows per block
constexpr int ROWSTR = 34;                        // smem row stride (words)
constexpr int PLANE = (TH + 2) * ROWSTR;          // 340 per channel-word plane
constexpr long long PIXWORDS = (long long)Nn * HP * WPAD * WORDS;
}

__device__ uint32_t g_s1[Nn * HP * WPAD * WORDS];
__device__ uint32_t g_z1[Nn * HP * WPAD * WORDS];
__device__ uint32_t g_s2[Nn * HP * WPAD * WORDS];
__device__ uint32_t g_z2[Nn * HP * WPAD * WORDS];
__device__ uint32_t g_wb1[C * KW];
__device__ uint32_t g_wb2[C * KW];
__device__ float g_sc1[C], g_sh1[C], g_sc2[C], g_sh2[C];

// Full adder: 3 words -> sum (weight w) + carry (weight 2w). One LOP3 each.
__device__ __forceinline__ void fa(uint32_t a, uint32_t b, uint32_t c,
                                   uint32_t& s, uint32_t& cy) {
    s = a ^ b ^ c;
    cy = (a & b) | (c & (a | b));
}
__device__ __forceinline__ void madacc2(int& a, int p) {  // a += 2*p (fma pipe)
    asm("mad.lo.s32 %0, %1, 2, %0;" : "+r"(a) : "r"(p));
}
__device__ __forceinline__ void madacc4(int& a, int p) {  // a += 4*p (fma pipe)
    asm("mad.lo.s32 %0, %1, 4, %0;" : "+r"(a) : "r"(p));
}
__device__ __forceinline__ int madn2(int acc, int d0) {   // d0 - 2*acc (fma pipe)
    int r;
    asm("mad.lo.s32 %0, %1, -2, %2;" : "=r"(r) : "r"(acc), "r"(d0));
    return r;
}

__global__ void k_zero_nz() {
    long long stride = (long long)gridDim.x * blockDim.x;
    for (long long i = blockIdx.x * (long long)blockDim.x + threadIdx.x;
         i < PIXWORDS; i += stride) {
        g_z1[i] = 0u;
        g_z2[i] = 0u;
    }
}

// Pack input activations: grid (H, N), block (W=56, WORDS=8).
__global__ void k_pack_x(const float* __restrict__ x) {
    const int h = blockIdx.x, n = blockIdx.y;
    const int w = threadIdx.x, wd = threadIdx.y;
    const float* xp = x + (((long long)n * C + wd * 32) * H + h) * W + w;
    uint32_t s = 0, z = 0;
#pragma unroll
    for (int ci = 0; ci < 32; ci++) {
        float v = xp[(long long)ci * (H * W)];
        s |= (v > 0.f ? 1u : 0u) << ci;
        z |= (v != 0.f ? 1u : 0u) << ci;
    }
    long long idx = (((long long)n * HP + (h + 1)) * WPAD + (w + 1)) * WORDS + wd;
    g_s1[idx] = s;
    g_z1[idx] = z;
}

// Pack weights: grid (C), block (WORDS=8, 9 taps).
__global__ void k_pack_w(const float* __restrict__ w, int which) {
    uint32_t* __restrict__ outw = which ? g_wb2 : g_wb1;
    const int co = blockIdx.x, wd = threadIdx.x, tap = threadIdx.y;
    uint32_t s = 0;
#pragma unroll
    for (int ci = 0; ci < 32; ci++)
        s |= (w[(((long long)co * C) + wd * 32 + ci) * 9 + tap] > 0.f ? 1u : 0u) << ci;
    outw[co * KW + tap * WORDS + wd] = s;
}

__global__ void k_prep_bn(const float* __restrict__ g, const float* __restrict__ b,
                          const float* __restrict__ m, const float* __restrict__ v,
                          int which) {
    int c = threadIdx.x;
    float sc = g[c] * rsqrtf(v[c] + BN_EPS);
    float sh = b[c] - m[c] * sc;
    if (which) { g_sc2[c] = sc; g_sh2[c] = sh; }
    else       { g_sc1[c] = sc; g_sh1[c] = sh; }
}

// Binary conv + BN (+ re-binarize or residual/clip), CSA-compressed popcount.
// Grid: (2 w-chunks, H/TH, N). Block: 256 threads = 8 warps.
// Warp lanes = output w; warp id = output channel word (32 co per warp).
// Inner step: 4 output channels share each x-window LDS pair.
template <int STAGE>
__global__ __launch_bounds__(256, 2) void k_bconv(
    const float* __restrict__ xres, float* __restrict__ out) {
    const uint32_t* __restrict__ sIn = (STAGE == 1) ? g_s1 : g_s2;
    const uint32_t* __restrict__ zIn = (STAGE == 1) ? g_z1 : g_z2;
    const uint32_t* __restrict__ wb = (STAGE == 1) ? g_wb1 : g_wb2;
    const float* __restrict__ gsc = (STAGE == 1) ? g_sc1 : g_sc2;
    const float* __restrict__ gsh = (STAGE == 1) ? g_sh1 : g_sh2;

    __shared__ uint32_t xs[WORDS * PLANE];
    __shared__ uint32_t xz[WORDS * PLANE];
    __shared__ float scs[C], shs[C];

    const int chunk = blockIdx.x, h0 = blockIdx.y * TH, n = blockIdx.z;
    const int tid = threadIdx.x, w0 = chunk * 32;

    for (int i = tid; i < WORDS * PLANE; i += 256) {
        int wd = i & 7, c = (i >> 3) % ROWSTR, r = (i >> 3) / ROWSTR;
        int col = w0 + c;
        uint32_t s = 0, z = 0;
        if (col < WPAD) {
            long long gi = (((long long)n * HP + (h0 + r)) * WPAD + col) * WORDS + wd;
            s = sIn[gi];
            z = zIn[gi];
        }
        xs[wd * PLANE + r * ROWSTR + c] = s;
        xz[wd * PLANE + r * ROWSTR + c] = z;
    }
    if (tid < C) { scs[tid] = gsc[tid]; shs[tid] = gsh[tid]; }
    __syncthreads();

    const int lane = tid & 31, wid = tid >> 5;
    const int ow = w0 + lane;
    const bool act = (ow < W);

    // base[r] = sum popc(nz) over the 72-word window (shared by all co), CSA'd.
    int base[TH];
#pragma unroll
    for (int r = 0; r < TH; r++) base[r] = 0;
    for (int g = 0; g < 8; g++) {
        int off[9];
#pragma unroll
        for (int q = 0; q < 9; q++) {
            int k = g * 9 + q;
            int wd = k & 7, tap = k >> 3;
            off[q] = wd * PLANE + (tap / 3) * ROWSTR + (tap % 3) + lane;
        }
#pragma unroll
        for (int r = 0; r < TH; r++) {
            uint32_t s0, c0, s1, c1, s2, c2, S, C2, S2, C4;
            fa(xz[off[0] + r * ROWSTR], xz[off[1] + r * ROWSTR], xz[off[2] + r * ROWSTR], s0, c0);
            fa(xz[off[3] + r * ROWSTR], xz[off[4] + r * ROWSTR], xz[off[5] + r * ROWSTR], s1, c1);
            fa(xz[off[6] + r * ROWSTR], xz[off[7] + r * ROWSTR], xz[off[8] + r * ROWSTR], s2, c2);
            fa(s0, s1, s2, S, C2);
            fa(c0, c1, c2, S2, C4);
            int a = base[r];
            a += __popc(S);
            madacc2(a, __popc(C2) + __popc(S2));
            madacc4(a, __popc(C4));
            base[r] = a;
        }
    }

    uint32_t osig[TH], onz[TH];
    if (STAGE == 1) {
#pragma unroll
        for (int r = 0; r < TH; r++) { osig[r] = 0u; onz[r] = 0u; }
    }

    for (int j0 = 0; j0 < 32; j0 += 4) {
        int acc[4][TH];
#pragma unroll
        for (int jj = 0; jj < 4; jj++)
#pragma unroll
            for (int r = 0; r < TH; r++) acc[jj][r] = 0;

        const uint32_t* wp = wb + (wid * 32 + j0) * KW;
        for (int g = 0; g < 8; g++) {
            uint32_t wk[4][9];
#pragma unroll
            for (int c4 = 0; c4 < 4; c4++)
#pragma unroll
                for (int t = 0; t < 9; t++) wk[c4][t] = __ldg(wp + c4 * KW + g * 9 + t);
            int off[9];
#pragma unroll
            for (int q = 0; q < 9; q++) {
                int k = g * 9 + q;
                int wd = k & 7, tap = k >> 3;
                off[q] = wd * PLANE + (tap / 3) * ROWSTR + (tap % 3) + lane;
            }
#pragma unroll
            for (int r = 0; r < TH; r++) {
                uint32_t sA[4][3], cA[4][3];
#pragma unroll
                for (int t3 = 0; t3 < 3; t3++) {
                    uint32_t sx0 = xs[off[t3 * 3 + 0] + r * ROWSTR];
                    uint32_t zx0 = xz[off[t3 * 3 + 0] + r * ROWSTR];
                    uint32_t sx1 = xs[off[t3 * 3 + 1] + r * ROWSTR];
                    uint32_t zx1 = xz[off[t3 * 3 + 1] + r * ROWSTR];
                    uint32_t sx2 = xs[off[t3 * 3 + 2] + r * ROWSTR];
                    uint32_t zx2 = xz[off[t3 * 3 + 2] + r * ROWSTR];
#pragma unroll
                    for (int c4 = 0; c4 < 4; c4++)
                        fa(zx0 & (sx0 ^ wk[c4][t3 * 3 + 0]),
                           zx1 & (sx1 ^ wk[c4][t3 * 3 + 1]),
                           zx2 & (sx2 ^ wk[c4][t3 * 3 + 2]),
                           sA[c4][t3], cA[c4][t3]);
                }
#pragma unroll
                for (int c4 = 0; c4 < 4; c4++) {
                    uint32_t S, C2, S2, C4w;
                    fa(sA[c4][0], sA[c4][1], sA[c4][2], S, C2);
                    fa(cA[c4][0], cA[c4][1], cA[c4][2], S2, C4w);
                    int a = acc[c4][r];
                    a += __popc(S);
                    madacc2(a, __popc(C2) + __popc(S2));
                    madacc4(a, __popc(C4w));
                    acc[c4][r] = a;
                }
            }
        }

#pragma unroll
        for (int jj = 0; jj < 4; jj++) {
            const int co = wid * 32 + j0 + jj;
            const float sc = scs[co], sh = shs[co];
            if (STAGE == 1) {
#pragma unroll
                for (int r = 0; r < TH; r++) {
                    const int dot = madn2(acc[jj][r], base[r]);
                    const float t = fmaf((float)dot, sc, sh);
                    osig[r] |= (t > 0.f ? 1u : 0u) << (j0 + jj);
                    onz[r] |= (t != 0.f ? 1u : 0u) << (j0 + jj);
                }
            } else if (act) {
#pragma unroll
                for (int r = 0; r < TH; r++) {
                    const int dot = madn2(acc[jj][r], base[r]);
                    const float t = fmaf((float)dot, sc, sh);
                    long long oi = (((long long)n * C + co) * H + (h0 + r)) * W + ow;
                    float v = t + xres[oi];
                    out[oi] = fminf(1.f, fmaxf(-1.f, v));
                }
            }
        }
    }

    if (STAGE == 1 && act) {
#pragma unroll
        for (int r = 0; r < TH; r++) {
            long long gi =
                (((long long)n * HP + (h0 + r + 1)) * WPAD + (ow + 1)) * WORDS + wid;
            g_s2[gi] = osig[r];
            g_z2[gi] = onz[r];
        }
    }
}

extern "C" void kernel_launch(void* const* d_in, const int* in_sizes, int n_in,
                              void* d_out, int out_size) {
    (void)in_sizes; (void)n_in; (void)out_size;
    const float* x = (const float*)d_in[0];
    const float* w1 = (const float*)d_in[1];
    const float* g1 = (const float*)d_in[2];
    const float* b1 = (const float*)d_in[3];
    const float* m1 = (const float*)d_in[4];
    const float* v1 = (const float*)d_in[5];
    const float* w2 = (const float*)d_in[6];
    const float* g2 = (const float*)d_in[7];
    const float* b2 = (const float*)d_in[8];
    const float* m2 = (const float*)d_in[9];
    const float* v2 = (const float*)d_in[10];
    float* out = (float*)d_out;

    dim3 grid(2, H / TH, Nn);
    // Launch order chosen so ncu (-s 5 -c 1) captures k_bconv1 (6th launch).
    k_zero_nz<<<1024, 256>>>();                        // 1
    k_pack_x<<<dim3(H, Nn), dim3(W, WORDS)>>>(x);      // 2
    k_pack_w<<<C, dim3(WORDS, 9)>>>(w1, 0);            // 3
    k_pack_w<<<C, dim3(WORDS, 9)>>>(w2, 1);            // 4
    k_prep_bn<<<1, C>>>(g1, b1, m1, v1, 0);            // 5
    k_bconv<1><<<grid, 256>>>(x, out);                 // 6  <- profiled
    k_prep_bn<<<1, C>>>(g2, b2, m2, v2, 1);            // 7
    k_bconv<2><<<grid, 256>>>(x, out);                 // 8
}